// round 4
// baseline (speedup 1.0000x reference)
#include <cuda_runtime.h>
#include <cstdint>
#include <cstddef>

// Problem constants (fixed by the dataset)
#define T_STEPS 512
#define BATCH   128
#define DIN     512
#define HID     512
#define G4      2048   // 4*HID

// ---------------------------------------------------------------------------
// Device-global scratch (allocation-free rule: __device__ arrays only).
// ---------------------------------------------------------------------------
__device__ float    g_xg[(size_t)T_STEPS * BATCH * G4];        // [T,B,4H] fp32
__device__ uint32_t g_xtf[(size_t)T_STEPS * BATCH * DIN];      // x as tf32 bits
__device__ uint32_t g_wxtf[(size_t)G4 * DIN];                  // Wx as tf32 bits
__device__ uint32_t g_hbuf[2][(size_t)BATCH * HID];            // h as tf32 bits, dbl-buf
__device__ unsigned int g_flag[4][T_STEPS][32];                // barrier flags
__device__ unsigned int g_exit;

// ---------------------------------------------------------------------------
// helpers
// ---------------------------------------------------------------------------
__device__ __forceinline__ uint32_t f2tf(float f) {
    uint32_t u;
    asm("cvt.rna.tf32.f32 %0, %1;" : "=r"(u) : "f"(f));
    return u;
}

__device__ __forceinline__ void mma_tf32(float* d,
    uint32_t a0, uint32_t a1, uint32_t a2, uint32_t a3,
    uint32_t b0, uint32_t b1)
{
    asm volatile(
        "mma.sync.aligned.m16n8k8.row.col.f32.tf32.tf32.f32 "
        "{%0,%1,%2,%3}, {%4,%5,%6,%7}, {%8,%9}, {%0,%1,%2,%3};\n"
        : "+f"(d[0]), "+f"(d[1]), "+f"(d[2]), "+f"(d[3])
        : "r"(a0), "r"(a1), "r"(a2), "r"(a3), "r"(b0), "r"(b1));
}

__device__ __forceinline__ void cp16(uint32_t dst, const void* src) {
    asm volatile("cp.async.cg.shared.global [%0], [%1], 16;" :: "r"(dst), "l"(src));
}
__device__ __forceinline__ void cp_commit() {
    asm volatile("cp.async.commit_group;");
}
template <int N>
__device__ __forceinline__ void cp_wait() {
    asm volatile("cp.async.wait_group %0;" :: "n"(N));
}

__device__ __forceinline__ float fsigmoid(float x) {
    return __fdividef(1.0f, 1.0f + __expf(-x));
}
__device__ __forceinline__ float ftanh(float x) {
    float e = __expf(-2.0f * x);
    return __fdividef(2.0f, 1.0f + e) - 1.0f;
}

// ===========================================================================
// Prologue: fp32 -> tf32-bits conversion (vectorized)
// ===========================================================================
__global__ void cvt_tf32_kernel(const float* __restrict__ src,
                                uint32_t* __restrict__ dst, size_t n4)
{
    size_t i = (size_t)blockIdx.x * blockDim.x + threadIdx.x;
    size_t stride = (size_t)gridDim.x * blockDim.x;
    for (; i < n4; i += stride) {
        float4 v = ((const float4*)src)[i];
        uint4  u;
        u.x = f2tf(v.x); u.y = f2tf(v.y); u.z = f2tf(v.z); u.w = f2tf(v.w);
        ((uint4*)dst)[i] = u;
    }
}

// ===========================================================================
// Phase A: xg[m][n] = sum_k x[m][k]*Wx[n][k] + bx[n] + bh[n]
//   Inputs already tf32 bits; tiles are raw u32, no CVT anywhere.
//   Block tile 128x128, BK=16, 256 threads, 2-stage cp.async pipeline.
// ===========================================================================
#define PA_W (128 * 20)
#define SMEM_A_BYTES (4 * PA_W * 4)

__global__ __launch_bounds__(256, 2) void gemm_xg_kernel(
    const float* __restrict__ bxp,
    const float* __restrict__ bhp)
{
    extern __shared__ uint32_t smA[];
    uint32_t* Asb[2] = { smA,            smA + PA_W };
    uint32_t* Bsb[2] = { smA + 2 * PA_W, smA + 3 * PA_W };

    const int tid  = threadIdx.x;
    const int bn   = blockIdx.x * 128;
    const int bm   = blockIdx.y * 128;
    const int warp = tid >> 5;
    const int lane = tid & 31;
    const int wm   = (warp & 3) * 32;
    const int wn   = (warp >> 2) * 64;
    const int g    = lane >> 2;
    const int t    = lane & 3;

    const uint32_t sbase = (uint32_t)__cvta_generic_to_shared(smA);

    float acc[2][8][4];
#pragma unroll
    for (int i = 0; i < 2; i++)
#pragma unroll
        for (int j = 0; j < 8; j++)
#pragma unroll
            for (int q = 0; q < 4; q++) acc[i][j][q] = 0.0f;

    auto issue_stage = [&](int k0, int s) {
#pragma unroll
        for (int i = 0; i < 2; i++) {
            int id = i * 256 + tid;
            int r  = id >> 2;
            int c4 = id & 3;
            uint32_t dA = sbase + (uint32_t)((s * PA_W + r * 20 + c4 * 4) * 4);
            cp16(dA, g_xtf + (size_t)(bm + r) * DIN + k0 + c4 * 4);
            uint32_t dB = sbase + (uint32_t)(((2 + s) * PA_W + r * 20 + c4 * 4) * 4);
            cp16(dB, g_wxtf + (size_t)(bn + r) * DIN + k0 + c4 * 4);
        }
        cp_commit();
    };

    issue_stage(0, 0);

    for (int it = 0; it < 32; it++) {
        if (it + 1 < 32) {
            issue_stage((it + 1) * 16, (it + 1) & 1);
            cp_wait<1>();
        } else {
            cp_wait<0>();
        }
        __syncthreads();

        const uint32_t* As = Asb[it & 1];
        const uint32_t* Bs = Bsb[it & 1];

#pragma unroll
        for (int kk = 0; kk < 2; kk++) {
            uint32_t a[2][4], b[8][2];
#pragma unroll
            for (int mt = 0; mt < 2; mt++) {
                int row = wm + mt * 16;
                a[mt][0] = As[(row + g    ) * 20 + kk * 8 + t];
                a[mt][1] = As[(row + g + 8) * 20 + kk * 8 + t];
                a[mt][2] = As[(row + g    ) * 20 + kk * 8 + t + 4];
                a[mt][3] = As[(row + g + 8) * 20 + kk * 8 + t + 4];
            }
#pragma unroll
            for (int nt = 0; nt < 8; nt++) {
                int col = wn + nt * 8 + g;
                b[nt][0] = Bs[col * 20 + kk * 8 + t];
                b[nt][1] = Bs[col * 20 + kk * 8 + t + 4];
            }
#pragma unroll
            for (int mt = 0; mt < 2; mt++)
#pragma unroll
                for (int nt = 0; nt < 8; nt++)
                    mma_tf32(acc[mt][nt],
                             a[mt][0], a[mt][1], a[mt][2], a[mt][3],
                             b[nt][0], b[nt][1]);
        }
        __syncthreads();
    }

#pragma unroll
    for (int mt = 0; mt < 2; mt++) {
        int row0 = bm + wm + mt * 16 + g;
#pragma unroll
        for (int nt = 0; nt < 8; nt++) {
            int col = bn + wn + nt * 8 + 2 * t;
            float bias0 = bxp[col]     + bhp[col];
            float bias1 = bxp[col + 1] + bhp[col + 1];
            float2 v0 = make_float2(acc[mt][nt][0] + bias0, acc[mt][nt][1] + bias1);
            float2 v1 = make_float2(acc[mt][nt][2] + bias0, acc[mt][nt][3] + bias1);
            *(float2*)(g_xg + (size_t)row0 * G4 + col)       = v0;
            *(float2*)(g_xg + (size_t)(row0 + 8) * G4 + col) = v1;
        }
    }
}

// ===========================================================================
// Phase B: persistent recurrent kernel, 128 blocks x 512 threads.
//   Block owns 32 batch rows x 16 h-cols. Wh slice (tf32) resident in SMEM.
//   16 warps, K-split 2: warp (kh, mt, npair) computes 1 m-tile x 2 n-tiles
//   over K/2; partials land in Gs0/Gs1 and the elementwise phase sums them.
//   h recurrence goes through tf32 g_hbuf (dbl-buffered); out is write-only.
//   Barrier: per-(bi,step) flag line, st.release / ld.acquire.
// ===========================================================================
#define WHS_WORDS (64 * 516)
#define HS_WORDS  (32 * 516)
#define GS_FLOATS (32 * 66)
#define CS_FLOATS (512)
#define SMEM_B_BYTES ((WHS_WORDS + HS_WORDS + 2 * GS_FLOATS + CS_FLOATS) * 4)

__global__ __launch_bounds__(512, 1) void lstm_rec_kernel(
    const float* __restrict__ Wh,
    float* __restrict__ out)
{
    extern __shared__ uint32_t smB[];
    uint32_t* Whs = smB;                                    // [64][516] tf32
    uint32_t* Hs  = smB + WHS_WORDS;                        // [32][516] tf32
    float*    Gs0 = (float*)(smB + WHS_WORDS + HS_WORDS);   // [32][66] partial (kh=0)
    float*    Gs1 = Gs0 + GS_FLOATS;                        // [32][66] partial (kh=1)
    float*    Cs  = Gs1 + GS_FLOATS;                        // [512] cell state

    const int tid  = threadIdx.x;
    const int warp = tid >> 5;
    const int lane = tid & 31;
    const int g    = lane >> 2;
    const int t    = lane & 3;

    const int bi = blockIdx.x >> 5;
    const int bj = blockIdx.x & 31;
    const int b0 = bi * 32;
    const int j0 = bj * 16;

    // one-time: Wh slice -> SMEM (tf32), c = 0
    for (int idx = tid; idx < 64 * 512; idx += 512) {
        int c = idx >> 9;
        int k = idx & 511;
        int gcol = (c >> 4) * HID + j0 + (c & 15);
        Whs[c * 516 + k] = f2tf(Wh[(size_t)gcol * HID + k]);
    }
    for (int i = tid; i < CS_FLOATS; i += 512) Cs[i] = 0.0f;
    __syncthreads();

    // warp mapping: kh = k-half, mt = m-tile, npair = pair of n-tiles
    const int kh    = warp >> 3;        // 0..1
    const int w8    = warp & 7;
    const int mt    = w8 & 1;           // 0..1
    const int npair = w8 >> 1;          // 0..3

    const int ko = kh * 256;            // k offset for this warp

    const uint32_t* Arow0 = Hs  + (mt * 16 + g) * 516 + ko;
    const uint32_t* Arow1 = Hs  + (mt * 16 + g + 8) * 516 + ko;
    const uint32_t* Brow0 = Whs + (npair * 16 + g) * 516 + ko;
    const uint32_t* Brow1 = Whs + (npair * 16 + 8 + g) * 516 + ko;
    float* GsK = (kh == 0) ? Gs0 : Gs1;

    // elementwise: one element per thread
    const int er = tid >> 4;            // 0..31 local batch row
    const int ej = tid & 15;            // 0..15 local h col

    const uint32_t hs_sm = (uint32_t)__cvta_generic_to_shared(Hs);

    // prefetch xg[0]
    float xr[4];
    {
        const float* xgp = g_xg + ((size_t)b0 + er) * G4 + j0 + ej;
        xr[0] = xgp[0]; xr[1] = xgp[HID]; xr[2] = xgp[2 * HID]; xr[3] = xgp[3 * HID];
    }

    for (int ts = 0; ts < T_STEPS; ts++) {
        if (ts > 0) {
            // ---- h_{t-1} (tf32 bits) -> SMEM via cp.async ----
            const uint32_t* hsrc = g_hbuf[(ts - 1) & 1] + (size_t)b0 * HID;
#pragma unroll
            for (int i = 0; i < 8; i++) {
                int id = i * 512 + tid;     // 0..4095 16B chunks
                int r  = id >> 7;
                int k4 = id & 127;
                cp16(hs_sm + (uint32_t)((r * 516 + k4 * 4) * 4),
                     hsrc + r * HID + k4 * 4);
            }
            cp_commit();
            cp_wait<0>();
            __syncthreads();

            // ---- 32x64x256 tf32 GEMM per k-half ----
            float ac0[4] = {0.f, 0.f, 0.f, 0.f};
            float ac1[4] = {0.f, 0.f, 0.f, 0.f};
            float bc0[4] = {0.f, 0.f, 0.f, 0.f};
            float bc1[4] = {0.f, 0.f, 0.f, 0.f};

#pragma unroll 2
            for (int kk = 0; kk < 32; kk += 2) {
                int kb = kk * 8 + t;
                {
                    uint32_t a0 = Arow0[kb],     a1 = Arow1[kb];
                    uint32_t a2 = Arow0[kb + 4], a3 = Arow1[kb + 4];
                    uint32_t p0 = Brow0[kb], p1 = Brow0[kb + 4];
                    uint32_t q0 = Brow1[kb], q1 = Brow1[kb + 4];
                    mma_tf32(ac0, a0, a1, a2, a3, p0, p1);
                    mma_tf32(ac1, a0, a1, a2, a3, q0, q1);
                }
                kb += 8;
                {
                    uint32_t a0 = Arow0[kb],     a1 = Arow1[kb];
                    uint32_t a2 = Arow0[kb + 4], a3 = Arow1[kb + 4];
                    uint32_t p0 = Brow0[kb], p1 = Brow0[kb + 4];
                    uint32_t q0 = Brow1[kb], q1 = Brow1[kb + 4];
                    mma_tf32(bc0, a0, a1, a2, a3, p0, p1);
                    mma_tf32(bc1, a0, a1, a2, a3, q0, q1);
                }
            }
#pragma unroll
            for (int q = 0; q < 4; q++) { ac0[q] += bc0[q]; ac1[q] += bc1[q]; }

            int row = mt * 16 + g;
            int c0  = npair * 16 + 2 * t;
            *(float2*)(GsK + row * 66 + c0)           = make_float2(ac0[0], ac0[1]);
            *(float2*)(GsK + (row + 8) * 66 + c0)     = make_float2(ac0[2], ac0[3]);
            *(float2*)(GsK + row * 66 + c0 + 8)       = make_float2(ac1[0], ac1[1]);
            *(float2*)(GsK + (row + 8) * 66 + c0 + 8) = make_float2(ac1[2], ac1[3]);
            __syncthreads();
        }

        // ---- elementwise gates (1 element per thread) ----
        float gi = xr[0], gf = xr[1], gg = xr[2], go = xr[3];
        if (ts > 0) {
            const float* r0 = Gs0 + er * 66;
            const float* r1 = Gs1 + er * 66;
            gi += r0[ej]      + r1[ej];
            gf += r0[16 + ej] + r1[16 + ej];
            gg += r0[32 + ej] + r1[32 + ej];
            go += r0[48 + ej] + r1[48 + ej];
        }
        float cprev = Cs[tid];
        float iv = fsigmoid(gi), fv = fsigmoid(gf), gv = ftanh(gg), ov = fsigmoid(go);
        float cn = cprev * fv + iv * gv;
        float h  = ov * ftanh(cn);
        Cs[tid] = cn;

        out[(size_t)ts * (BATCH * HID) + (size_t)(b0 + er) * HID + j0 + ej] = h;
        g_hbuf[ts & 1][(size_t)(b0 + er) * HID + j0 + ej] = f2tf(h);

        __syncthreads();   // all stores program-ordered before the release below

        if (ts < T_STEPS - 1) {
            // prefetch xg[ts+1] while the barrier propagates
            const float* xgp = g_xg + ((size_t)(ts + 1) * BATCH + b0 + er) * G4 + j0 + ej;
            xr[0] = xgp[0]; xr[1] = xgp[HID]; xr[2] = xgp[2 * HID]; xr[3] = xgp[3 * HID];

            // ---- flag-broadcast barrier over the 32 same-bi blocks ----
            if (tid == 0) {
                asm volatile("st.release.gpu.global.u32 [%0], %1;"
                             :: "l"(&g_flag[bi][ts][bj]), "r"(1u) : "memory");
            }
            if (tid < 32) {
                const unsigned int* fp = &g_flag[bi][ts][tid];
                unsigned v;
                do {
                    asm volatile("ld.acquire.gpu.global.u32 %0, [%1];"
                                 : "=r"(v) : "l"(fp) : "memory");
                    if (v) break;
                    __nanosleep(32);
                } while (true);
            }
            __syncthreads();
        }
    }

    // ---- exit: last block resets barrier state for the next graph replay ----
    __syncthreads();
    if (tid == 0) {
        unsigned old;
        asm volatile("atom.acq_rel.gpu.add.u32 %0, [%1], 1;"
                     : "=r"(old) : "l"(&g_exit) : "memory");
        Gs0[0] = (old == 127u) ? 1.0f : 0.0f;
    }
    __syncthreads();
    if (Gs0[0] != 0.0f) {
        unsigned int* fl = &g_flag[0][0][0];
        for (int i = tid; i < 4 * T_STEPS * 32; i += 512) fl[i] = 0u;
        __threadfence();
        if (tid == 0) g_exit = 0u;
    }
}

// ===========================================================================
// Launch
// ===========================================================================
extern "C" void kernel_launch(void* const* d_in, const int* in_sizes, int n_in,
                              void* d_out, int out_size)
{
    (void)in_sizes; (void)n_in; (void)out_size;
    const float* x  = (const float*)d_in[0];
    const float* Wx = (const float*)d_in[1];
    const float* bx = (const float*)d_in[2];
    const float* Wh = (const float*)d_in[3];
    const float* bh = (const float*)d_in[4];
    float* out = (float*)d_out;

    uint32_t* xtf;  cudaGetSymbolAddress((void**)&xtf,  g_xtf);
    uint32_t* wxtf; cudaGetSymbolAddress((void**)&wxtf, g_wxtf);

    cudaFuncSetAttribute(gemm_xg_kernel,
                         cudaFuncAttributeMaxDynamicSharedMemorySize,
                         SMEM_A_BYTES);
    cudaFuncSetAttribute(lstm_rec_kernel,
                         cudaFuncAttributeMaxDynamicSharedMemorySize,
                         SMEM_B_BYTES);

    // Prologue: convert x and Wx to tf32 bits
    cvt_tf32_kernel<<<2048, 256>>>(x,  xtf,  (size_t)T_STEPS * BATCH * DIN / 4);
    cvt_tf32_kernel<<<512,  256>>>(Wx, wxtf, (size_t)G4 * DIN / 4);

    // Phase A
    gemm_xg_kernel<<<dim3(G4 / 128, (T_STEPS * BATCH) / 128), 256, SMEM_A_BYTES>>>(bx, bh);

    // Phase B
    lstm_rec_kernel<<<128, 512, SMEM_B_BYTES>>>(Wh, out);
}

// round 6
// speedup vs baseline: 1.4005x; 1.4005x over previous
#include <cuda_runtime.h>
#include <cuda_fp16.h>
#include <cstdint>
#include <cstddef>

// Problem constants
#define T_STEPS 512
#define BATCH   128
#define DIN     512
#define HID     512
#define G4      2048   // 4*HID

// ---------------------------------------------------------------------------
// Device-global scratch (allocation-free rule)
// ---------------------------------------------------------------------------
__device__ float  g_xg[(size_t)T_STEPS * BATCH * G4];     // [T,B,4H] fp32
__device__ __half g_xh[(size_t)T_STEPS * BATCH * DIN];    // x as fp16
__device__ __half g_wxh[(size_t)G4 * DIN];                // Wx as fp16
__device__ __half g_hbuf[2][(size_t)BATCH * HID];         // h as fp16, dbl-buf
__device__ unsigned int g_flag[4][T_STEPS][32];           // barrier flags
__device__ unsigned int g_exit;

// ---------------------------------------------------------------------------
// helpers
// ---------------------------------------------------------------------------
__device__ __forceinline__ void mma_f16(float* d,
    uint32_t a0, uint32_t a1, uint32_t a2, uint32_t a3,
    uint32_t b0, uint32_t b1)
{
    asm volatile(
        "mma.sync.aligned.m16n8k16.row.col.f32.f16.f16.f32 "
        "{%0,%1,%2,%3}, {%4,%5,%6,%7}, {%8,%9}, {%0,%1,%2,%3};\n"
        : "+f"(d[0]), "+f"(d[1]), "+f"(d[2]), "+f"(d[3])
        : "r"(a0), "r"(a1), "r"(a2), "r"(a3), "r"(b0), "r"(b1));
}

__device__ __forceinline__ void ldsm4(uint32_t* r, uint32_t addr) {
    asm volatile(
        "ldmatrix.sync.aligned.m8n8.x4.shared.b16 {%0,%1,%2,%3}, [%4];"
        : "=r"(r[0]), "=r"(r[1]), "=r"(r[2]), "=r"(r[3]) : "r"(addr));
}

__device__ __forceinline__ void cp16(uint32_t dst, const void* src) {
    asm volatile("cp.async.cg.shared.global [%0], [%1], 16;" :: "r"(dst), "l"(src));
}
__device__ __forceinline__ void cp_commit() {
    asm volatile("cp.async.commit_group;");
}
template <int N>
__device__ __forceinline__ void cp_wait() {
    asm volatile("cp.async.wait_group %0;" :: "n"(N));
}

__device__ __forceinline__ float fsigmoid(float x) {
    return __fdividef(1.0f, 1.0f + __expf(-x));
}
__device__ __forceinline__ float ftanh(float x) {
    float e = __expf(-2.0f * x);
    return __fdividef(2.0f, 1.0f + e) - 1.0f;
}

// ===========================================================================
// Prologue: fp32 -> fp16 conversion
// ===========================================================================
__global__ void cvt_f16_kernel(const float* __restrict__ src,
                               __half* __restrict__ dst, size_t n4)
{
    size_t i = (size_t)blockIdx.x * blockDim.x + threadIdx.x;
    size_t stride = (size_t)gridDim.x * blockDim.x;
    for (; i < n4; i += stride) {
        float4 v = ((const float4*)src)[i];
        __half2 lo = __floats2half2_rn(v.x, v.y);
        __half2 hi = __floats2half2_rn(v.z, v.w);
        uint2 u;
        u.x = *(uint32_t*)&lo;
        u.y = *(uint32_t*)&hi;
        ((uint2*)dst)[i] = u;
    }
}

// ===========================================================================
// Phase A: xg[m][n] = sum_k x[m][k]*Wx[n][k] + bx[n] + bh[n]   (fp16 mma)
//   M=65536, N=2048, K=512. Block 128x128, BK=32, 256 threads, 2-stage
//   cp.async. SMEM pitch 80B (32 halves + 16B pad): ldmatrix conflict-free.
//   Warp tile 32m x 64n. Fragments via ldmatrix.x4.
// ===========================================================================
#define PA_PITCH 80
#define PA_STG   (128 * PA_PITCH)            // 10240 B per tile stage
#define SMEM_A_BYTES (4 * PA_STG)            // A0|A1|B0|B1 = 40960 B

__global__ __launch_bounds__(256, 2) void gemm_xg_kernel(
    const float* __restrict__ bxp,
    const float* __restrict__ bhp)
{
    extern __shared__ uint8_t smA[];
    const uint32_t sb = (uint32_t)__cvta_generic_to_shared(smA);

    const int tid  = threadIdx.x;
    const int bn   = blockIdx.x * 128;
    const int bm   = blockIdx.y * 128;
    const int warp = tid >> 5;
    const int lane = tid & 31;
    const int wm   = (warp & 3) * 32;
    const int wn   = (warp >> 2) * 64;
    const int g    = lane >> 2;
    const int t    = lane & 3;

    float acc[2][8][4];
#pragma unroll
    for (int i = 0; i < 2; i++)
#pragma unroll
        for (int j = 0; j < 8; j++)
#pragma unroll
            for (int q = 0; q < 4; q++) acc[i][j][q] = 0.0f;

    // ldmatrix base addresses (within a stage)
    // A x4: lanes 0-15 -> rows (lane&15), lanes 16-31 -> same rows, +16B col
    uint32_t aA0 = (uint32_t)((wm + (lane & 15)) * PA_PITCH + (lane >> 4) * 16);
    uint32_t aA1 = (uint32_t)((wm + 16 + (lane & 15)) * PA_PITCH + (lane >> 4) * 16);
    // B x4: rows n = wn + nt4*16 + (lane&7) + (lane>=16 ? 8 : 0), col16 = (lane>>3)&1
    uint32_t brow = (uint32_t)(wn + (lane & 7) + ((lane >> 4) << 3));
    uint32_t bcol = (uint32_t)(((lane >> 3) & 1) * 16);

    auto issue_stage = [&](int k0, int s) {
        // A: 128 rows x 4 16B-chunks; B same. 1024 chunks / 256 thr = 4 each.
#pragma unroll
        for (int i = 0; i < 2; i++) {
            int id = i * 256 + tid;
            int r  = id >> 2;
            int u  = id & 3;
            cp16(sb + (uint32_t)(s * PA_STG + r * PA_PITCH + u * 16),
                 g_xh + (size_t)(bm + r) * DIN + k0 + u * 8);
            cp16(sb + (uint32_t)((2 + s) * PA_STG + r * PA_PITCH + u * 16),
                 g_wxh + (size_t)(bn + r) * DIN + k0 + u * 8);
        }
        cp_commit();
    };

    issue_stage(0, 0);

    for (int it = 0; it < 16; it++) {
        if (it + 1 < 16) {
            issue_stage((it + 1) * 32, (it + 1) & 1);
            cp_wait<1>();
        } else {
            cp_wait<0>();
        }
        __syncthreads();

        uint32_t As = sb + (uint32_t)((it & 1) * PA_STG);
        uint32_t Bs = sb + (uint32_t)((2 + (it & 1)) * PA_STG);

#pragma unroll
        for (int kk = 0; kk < 2; kk++) {
            uint32_t koff = (uint32_t)(kk * 32);
            uint32_t a[2][4], bb[4][4];
            ldsm4(a[0], As + aA0 + koff);
            ldsm4(a[1], As + aA1 + koff);
#pragma unroll
            for (int nt4 = 0; nt4 < 4; nt4++)
                ldsm4(bb[nt4], Bs + (brow + nt4 * 16) * PA_PITCH + bcol + koff);
#pragma unroll
            for (int mt = 0; mt < 2; mt++)
#pragma unroll
                for (int nt = 0; nt < 8; nt++)
                    mma_f16(acc[mt][nt],
                            a[mt][0], a[mt][1], a[mt][2], a[mt][3],
                            bb[nt >> 1][(nt & 1) * 2], bb[nt >> 1][(nt & 1) * 2 + 1]);
        }
        __syncthreads();
    }

    // epilogue: add biases, store fp32 xg
#pragma unroll
    for (int mt = 0; mt < 2; mt++) {
        int row0 = bm + wm + mt * 16 + g;
#pragma unroll
        for (int nt = 0; nt < 8; nt++) {
            int col = bn + wn + nt * 8 + 2 * t;
            float bias0 = bxp[col]     + bhp[col];
            float bias1 = bxp[col + 1] + bhp[col + 1];
            float2 v0 = make_float2(acc[mt][nt][0] + bias0, acc[mt][nt][1] + bias1);
            float2 v1 = make_float2(acc[mt][nt][2] + bias0, acc[mt][nt][3] + bias1);
            *(float2*)(g_xg + (size_t)row0 * G4 + col)       = v0;
            *(float2*)(g_xg + (size_t)(row0 + 8) * G4 + col) = v1;
        }
    }
}

// ===========================================================================
// Phase B: persistent fp16 recurrent kernel, 128 blocks x 256 threads.
//   Block (bi,bj) owns 32 batch rows x 16 h-cols (64 gate cols).
//   Wh slice [64][512] fp16 resident in SMEM (pitch 1040B, conflict-free).
//   Per step: cp.async h tile (fp16, 32KB) -> SMEM; 4 mma warps (32m x 16n
//   each) via ldmatrix.x4; gates -> Gs; elementwise (c in regs); h -> out
//   (fp32) + g_hbuf (fp16); flag-broadcast barrier over same-bi blocks.
// ===========================================================================
#define PB_PITCH 1040                               // 512 halves + 16B pad
#define WHS_OFF  0u
#define HS_OFF   (64u * PB_PITCH)                   // 66560
#define GS_OFF   (HS_OFF + 32u * PB_PITCH)          // 99840
#define GS_FLOATS (32 * 66)
#define SMEM_B_BYTES (GS_OFF + GS_FLOATS * 4)       // 108288

__global__ __launch_bounds__(256, 1) void lstm_rec_kernel(
    const float* __restrict__ Wh,
    float* __restrict__ out)
{
    extern __shared__ uint8_t smB[];
    const uint32_t sb = (uint32_t)__cvta_generic_to_shared(smB);
    float* Gs = (float*)(smB + GS_OFF);

    const int tid  = threadIdx.x;
    const int warp = tid >> 5;
    const int lane = tid & 31;
    const int g    = lane >> 2;
    const int t    = lane & 3;

    const int bi = blockIdx.x >> 5;
    const int bj = blockIdx.x & 31;
    const int b0 = bi * 32;
    const int j0 = bj * 16;

    // one-time: Wh slice -> SMEM fp16. Local gate col n: gate=n>>4, col=n&15.
    for (int idx = tid; idx < 64 * 512; idx += 256) {
        int n = idx >> 9;
        int k = idx & 511;
        int grow = (n >> 4) * HID + j0 + (n & 15);
        *(__half*)(smB + WHS_OFF + (uint32_t)n * PB_PITCH + (uint32_t)k * 2) =
            __float2half_rn(Wh[(size_t)grow * HID + k]);
    }
    __syncthreads();

    // mma warps 0-3: warp w covers all 32 m rows x n in [w*16, w*16+16)
    // ldmatrix bases:
    uint32_t aA0 = sb + HS_OFF + (uint32_t)((lane & 15) * PB_PITCH + (lane >> 4) * 16);
    uint32_t aA1 = sb + HS_OFF + (uint32_t)((16 + (lane & 15)) * PB_PITCH + (lane >> 4) * 16);
    uint32_t aB  = sb + WHS_OFF
                 + (uint32_t)((warp * 16 + (lane & 7) + ((lane >> 4) << 3)) * PB_PITCH
                              + ((lane >> 3) & 1) * 16);

    // elementwise mapping: thread -> elements (er, ej), (er, ej+1)
    const int e0 = tid * 2;
    const int er = e0 >> 4;
    const int ej = e0 & 15;

    float cst0 = 0.0f, cst1 = 0.0f;     // cell state in registers

    // prefetch xg[0]
    float xr[8];
    {
        const float* xgp = g_xg + ((size_t)b0 + er) * G4 + j0;
        float2 v;
        v = *(const float2*)(xgp + ej);            xr[0] = v.x; xr[1] = v.y;
        v = *(const float2*)(xgp + HID + ej);      xr[2] = v.x; xr[3] = v.y;
        v = *(const float2*)(xgp + 2 * HID + ej);  xr[4] = v.x; xr[5] = v.y;
        v = *(const float2*)(xgp + 3 * HID + ej);  xr[6] = v.x; xr[7] = v.y;
    }

    for (int ts = 0; ts < T_STEPS; ts++) {
        if (ts > 0) {
            // ---- h_{t-1} fp16 tile -> SMEM (32 rows x 1024B) ----
            const __half* hsrc = g_hbuf[(ts - 1) & 1] + (size_t)b0 * HID;
#pragma unroll
            for (int i = 0; i < 8; i++) {
                int id = i * 256 + tid;      // 0..2047 16B chunks
                int r  = id >> 6;
                int u  = id & 63;
                cp16(sb + HS_OFF + (uint32_t)(r * PB_PITCH + u * 16),
                     hsrc + (size_t)r * HID + u * 8);
            }
            cp_commit();
            cp_wait<0>();
            __syncthreads();

            // ---- 32x64x512 fp16 GEMM: 4 warps, 32 k16-steps ----
            if (warp < 4) {
                float acc[2][2][4];
#pragma unroll
                for (int mt = 0; mt < 2; mt++)
#pragma unroll
                    for (int nt = 0; nt < 2; nt++)
#pragma unroll
                        for (int q = 0; q < 4; q++) acc[mt][nt][q] = 0.0f;

#pragma unroll 4
                for (int s = 0; s < 32; s++) {
                    uint32_t ko = (uint32_t)(s * 32);
                    uint32_t a0[4], a1[4], bb[4];
                    ldsm4(a0, aA0 + ko);
                    ldsm4(a1, aA1 + ko);
                    ldsm4(bb, aB + ko);
                    mma_f16(acc[0][0], a0[0], a0[1], a0[2], a0[3], bb[0], bb[1]);
                    mma_f16(acc[0][1], a0[0], a0[1], a0[2], a0[3], bb[2], bb[3]);
                    mma_f16(acc[1][0], a1[0], a1[1], a1[2], a1[3], bb[0], bb[1]);
                    mma_f16(acc[1][1], a1[0], a1[1], a1[2], a1[3], bb[2], bb[3]);
                }

                // accumulators -> Gs
#pragma unroll
                for (int mt = 0; mt < 2; mt++) {
                    int row = mt * 16 + g;
#pragma unroll
                    for (int nt = 0; nt < 2; nt++) {
                        int c0 = warp * 16 + nt * 8 + 2 * t;
                        *(float2*)(Gs + row * 66 + c0) =
                            make_float2(acc[mt][nt][0], acc[mt][nt][1]);
                        *(float2*)(Gs + (row + 8) * 66 + c0) =
                            make_float2(acc[mt][nt][2], acc[mt][nt][3]);
                    }
                }
            }
            __syncthreads();
        }

        // ---- elementwise gates: 2 elements per thread ----
        float gi0 = xr[0], gi1 = xr[1];
        float gf0 = xr[2], gf1 = xr[3];
        float gg0 = xr[4], gg1 = xr[5];
        float go0 = xr[6], go1 = xr[7];
        if (ts > 0) {
            const float* gr = Gs + er * 66;
            float2 v;
            v = *(const float2*)(gr + ej);        gi0 += v.x; gi1 += v.y;
            v = *(const float2*)(gr + 16 + ej);   gf0 += v.x; gf1 += v.y;
            v = *(const float2*)(gr + 32 + ej);   gg0 += v.x; gg1 += v.y;
            v = *(const float2*)(gr + 48 + ej);   go0 += v.x; go1 += v.y;
        }
        float i0 = fsigmoid(gi0), f0 = fsigmoid(gf0), gt0 = ftanh(gg0), o0 = fsigmoid(go0);
        float i1 = fsigmoid(gi1), f1 = fsigmoid(gf1), gt1 = ftanh(gg1), o1 = fsigmoid(go1);
        float cn0 = cst0 * f0 + i0 * gt0;
        float cn1 = cst1 * f1 + i1 * gt1;
        float h0 = o0 * ftanh(cn0);
        float h1 = o1 * ftanh(cn1);
        cst0 = cn0; cst1 = cn1;

        float* orow = out + (size_t)ts * (BATCH * HID) + (size_t)(b0 + er) * HID + j0;
        *(float2*)(orow + ej) = make_float2(h0, h1);

        __half2 hh = __floats2half2_rn(h0, h1);
        *(uint32_t*)(g_hbuf[ts & 1] + (size_t)(b0 + er) * HID + j0 + ej) =
            *(uint32_t*)&hh;

        __syncthreads();   // all h stores program-ordered before the release

        if (ts < T_STEPS - 1) {
            // release arrival
            if (tid == 0) {
                asm volatile("st.release.gpu.global.u32 [%0], %1;"
                             :: "l"(&g_flag[bi][ts][bj]), "r"(1u) : "memory");
            }
            // prefetch xg[ts+1] while the barrier propagates
            {
                const float* xgp =
                    g_xg + ((size_t)(ts + 1) * BATCH + b0 + er) * G4 + j0;
                float2 v;
                v = *(const float2*)(xgp + ej);            xr[0] = v.x; xr[1] = v.y;
                v = *(const float2*)(xgp + HID + ej);      xr[2] = v.x; xr[3] = v.y;
                v = *(const float2*)(xgp + 2 * HID + ej);  xr[4] = v.x; xr[5] = v.y;
                v = *(const float2*)(xgp + 3 * HID + ej);  xr[6] = v.x; xr[7] = v.y;
            }
            // wait for all 32 same-bi blocks
            if (tid < 32) {
                const unsigned int* fp = &g_flag[bi][ts][tid];
                unsigned v;
                do {
                    asm volatile("ld.acquire.gpu.global.u32 %0, [%1];"
                                 : "=r"(v) : "l"(fp) : "memory");
                    if (v) break;
                    __nanosleep(32);
                } while (true);
            }
            __syncthreads();
        }
    }

    // ---- exit: last block resets barrier state for next graph replay ----
    __syncthreads();
    if (tid == 0) {
        unsigned old;
        asm volatile("atom.acq_rel.gpu.add.u32 %0, [%1], 1;"
                     : "=r"(old) : "l"(&g_exit) : "memory");
        Gs[0] = (old == 127u) ? 1.0f : 0.0f;
    }
    __syncthreads();
    if (Gs[0] != 0.0f) {
        unsigned int* fl = &g_flag[0][0][0];
        for (int i = tid; i < 4 * T_STEPS * 32; i += 256) fl[i] = 0u;
        __threadfence();
        if (tid == 0) g_exit = 0u;
    }
}

// ===========================================================================
// Launch
// ===========================================================================
extern "C" void kernel_launch(void* const* d_in, const int* in_sizes, int n_in,
                              void* d_out, int out_size)
{
    (void)in_sizes; (void)n_in; (void)out_size;
    const float* x  = (const float*)d_in[0];
    const float* Wx = (const float*)d_in[1];
    const float* bx = (const float*)d_in[2];
    const float* Wh = (const float*)d_in[3];
    const float* bh = (const float*)d_in[4];
    float* out = (float*)d_out;

    __half* xh;  cudaGetSymbolAddress((void**)&xh,  g_xh);
    __half* wxh; cudaGetSymbolAddress((void**)&wxh, g_wxh);

    cudaFuncSetAttribute(gemm_xg_kernel,
                         cudaFuncAttributeMaxDynamicSharedMemorySize, SMEM_A_BYTES);
    cudaFuncSetAttribute(lstm_rec_kernel,
                         cudaFuncAttributeMaxDynamicSharedMemorySize, SMEM_B_BYTES);

    // Prologue: fp32 -> fp16
    cvt_f16_kernel<<<2048, 256>>>(x,  xh,  (size_t)T_STEPS * BATCH * DIN / 4);
    cvt_f16_kernel<<<512,  256>>>(Wx, wxh, (size_t)G4 * DIN / 4);

    // Phase A
    gemm_xg_kernel<<<dim3(G4 / 128, (T_STEPS * BATCH) / 128), 256, SMEM_A_BYTES>>>(bx, bh);

    // Phase B
    lstm_rec_kernel<<<128, 256, SMEM_B_BYTES>>>(Wh, out);
}

// round 7
// speedup vs baseline: 1.6698x; 1.1923x over previous
#include <cuda_runtime.h>
#include <cuda_fp16.h>
#include <cstdint>
#include <cstddef>

// Problem constants
#define T_STEPS 512
#define BATCH   128
#define DIN     512
#define HID     512
#define G4      2048   // 4*HID

// ---------------------------------------------------------------------------
// Device-global scratch (allocation-free rule)
// ---------------------------------------------------------------------------
__device__ float  g_xg[(size_t)T_STEPS * BATCH * G4];     // [T,B,4H] fp32
__device__ __half g_xh[(size_t)T_STEPS * BATCH * DIN];    // x as fp16
__device__ __half g_wxh[(size_t)G4 * DIN];                // Wx as fp16
__device__ __half g_hbuf[2][(size_t)BATCH * HID];         // h as fp16, dbl-buf
__device__ unsigned int g_flag[4][T_STEPS][32];           // barrier flags
__device__ unsigned int g_exit;

// ---------------------------------------------------------------------------
// helpers
// ---------------------------------------------------------------------------
__device__ __forceinline__ void mma_f16(float* d,
    uint32_t a0, uint32_t a1, uint32_t a2, uint32_t a3,
    uint32_t b0, uint32_t b1)
{
    asm volatile(
        "mma.sync.aligned.m16n8k16.row.col.f32.f16.f16.f32 "
        "{%0,%1,%2,%3}, {%4,%5,%6,%7}, {%8,%9}, {%0,%1,%2,%3};\n"
        : "+f"(d[0]), "+f"(d[1]), "+f"(d[2]), "+f"(d[3])
        : "r"(a0), "r"(a1), "r"(a2), "r"(a3), "r"(b0), "r"(b1));
}

__device__ __forceinline__ void ldsm4(uint32_t* r, uint32_t addr) {
    asm volatile(
        "ldmatrix.sync.aligned.m8n8.x4.shared.b16 {%0,%1,%2,%3}, [%4];"
        : "=r"(r[0]), "=r"(r[1]), "=r"(r[2]), "=r"(r[3]) : "r"(addr));
}

__device__ __forceinline__ void cp16(uint32_t dst, const void* src) {
    asm volatile("cp.async.cg.shared.global [%0], [%1], 16;" :: "r"(dst), "l"(src));
}
__device__ __forceinline__ void cp_commit() {
    asm volatile("cp.async.commit_group;");
}
template <int N>
__device__ __forceinline__ void cp_wait() {
    asm volatile("cp.async.wait_group %0;" :: "n"(N));
}

__device__ __forceinline__ float fsigmoid(float x) {
    return __fdividef(1.0f, 1.0f + __expf(-x));
}
__device__ __forceinline__ float ftanh(float x) {
    float e = __expf(-2.0f * x);
    return __fdividef(2.0f, 1.0f + e) - 1.0f;
}

// ===========================================================================
// Prologue: fp32 -> fp16 conversion
// ===========================================================================
__global__ void cvt_f16_kernel(const float* __restrict__ src,
                               __half* __restrict__ dst, size_t n4)
{
    size_t i = (size_t)blockIdx.x * blockDim.x + threadIdx.x;
    size_t stride = (size_t)gridDim.x * blockDim.x;
    for (; i < n4; i += stride) {
        float4 v = ((const float4*)src)[i];
        __half2 lo = __floats2half2_rn(v.x, v.y);
        __half2 hi = __floats2half2_rn(v.z, v.w);
        uint2 u;
        u.x = *(uint32_t*)&lo;
        u.y = *(uint32_t*)&hi;
        ((uint2*)dst)[i] = u;
    }
}

// ===========================================================================
// Phase A: xg[m][n] = sum_k x[m][k]*Wx[n][k] + bx[n] + bh[n]   (fp16 mma)
//   (unchanged from round 6 — proven)
// ===========================================================================
#define PA_PITCH 80
#define PA_STG   (128 * PA_PITCH)
#define SMEM_A_BYTES (4 * PA_STG)

__global__ __launch_bounds__(256, 2) void gemm_xg_kernel(
    const float* __restrict__ bxp,
    const float* __restrict__ bhp)
{
    extern __shared__ uint8_t smA[];
    const uint32_t sb = (uint32_t)__cvta_generic_to_shared(smA);

    const int tid  = threadIdx.x;
    const int bn   = blockIdx.x * 128;
    const int bm   = blockIdx.y * 128;
    const int warp = tid >> 5;
    const int lane = tid & 31;
    const int wm   = (warp & 3) * 32;
    const int wn   = (warp >> 2) * 64;
    const int g    = lane >> 2;
    const int t    = lane & 3;

    float acc[2][8][4];
#pragma unroll
    for (int i = 0; i < 2; i++)
#pragma unroll
        for (int j = 0; j < 8; j++)
#pragma unroll
            for (int q = 0; q < 4; q++) acc[i][j][q] = 0.0f;

    uint32_t aA0 = (uint32_t)((wm + (lane & 15)) * PA_PITCH + (lane >> 4) * 16);
    uint32_t aA1 = (uint32_t)((wm + 16 + (lane & 15)) * PA_PITCH + (lane >> 4) * 16);
    uint32_t brow = (uint32_t)(wn + (lane & 7) + ((lane >> 4) << 3));
    uint32_t bcol = (uint32_t)(((lane >> 3) & 1) * 16);

    auto issue_stage = [&](int k0, int s) {
#pragma unroll
        for (int i = 0; i < 2; i++) {
            int id = i * 256 + tid;
            int r  = id >> 2;
            int u  = id & 3;
            cp16(sb + (uint32_t)(s * PA_STG + r * PA_PITCH + u * 16),
                 g_xh + (size_t)(bm + r) * DIN + k0 + u * 8);
            cp16(sb + (uint32_t)((2 + s) * PA_STG + r * PA_PITCH + u * 16),
                 g_wxh + (size_t)(bn + r) * DIN + k0 + u * 8);
        }
        cp_commit();
    };

    issue_stage(0, 0);

    for (int it = 0; it < 16; it++) {
        if (it + 1 < 16) {
            issue_stage((it + 1) * 32, (it + 1) & 1);
            cp_wait<1>();
        } else {
            cp_wait<0>();
        }
        __syncthreads();

        uint32_t As = sb + (uint32_t)((it & 1) * PA_STG);
        uint32_t Bs = sb + (uint32_t)((2 + (it & 1)) * PA_STG);

#pragma unroll
        for (int kk = 0; kk < 2; kk++) {
            uint32_t koff = (uint32_t)(kk * 32);
            uint32_t a[2][4], bb[4][4];
            ldsm4(a[0], As + aA0 + koff);
            ldsm4(a[1], As + aA1 + koff);
#pragma unroll
            for (int nt4 = 0; nt4 < 4; nt4++)
                ldsm4(bb[nt4], Bs + (brow + nt4 * 16) * PA_PITCH + bcol + koff);
#pragma unroll
            for (int mt = 0; mt < 2; mt++)
#pragma unroll
                for (int nt = 0; nt < 8; nt++)
                    mma_f16(acc[mt][nt],
                            a[mt][0], a[mt][1], a[mt][2], a[mt][3],
                            bb[nt >> 1][(nt & 1) * 2], bb[nt >> 1][(nt & 1) * 2 + 1]);
        }
        __syncthreads();
    }

#pragma unroll
    for (int mt = 0; mt < 2; mt++) {
        int row0 = bm + wm + mt * 16 + g;
#pragma unroll
        for (int nt = 0; nt < 8; nt++) {
            int col = bn + wn + nt * 8 + 2 * t;
            float bias0 = bxp[col]     + bhp[col];
            float bias1 = bxp[col + 1] + bhp[col + 1];
            float2 v0 = make_float2(acc[mt][nt][0] + bias0, acc[mt][nt][1] + bias1);
            float2 v1 = make_float2(acc[mt][nt][2] + bias0, acc[mt][nt][3] + bias1);
            *(float2*)(g_xg + (size_t)row0 * G4 + col)       = v0;
            *(float2*)(g_xg + (size_t)(row0 + 8) * G4 + col) = v1;
        }
    }
}

// ===========================================================================
// Phase B: persistent fp16 recurrent kernel, 128 blocks x 128 threads.
//   Block (bi,bj) owns 32 batch rows x 16 h-cols. 4 mma warps; warp w owns
//   h-cols [j0+w*4, j0+w*4+4) with B rows GATE-INTERLEAVED
//   [i0 f0 g0 o0 i1 f1 g1 o1 | i2 f2 g2 o2 i3 f3 g3 o3] so that after the
//   GEMM one shfl.xor(1) pair completes every gate quadruple inside the warp
//   (no Gs SMEM round-trip, no extra syncthreads).
//   xg is staged to SMEM (Xs, dbl-buffered) via cp.async issued during the
//   previous step's poll window. out fp32 stores happen after the release.
// ===========================================================================
#define PB_PITCH 1040                               // 512 halves + 16B pad
#define WHS_OFF  0u
#define HS_OFF   (64u * PB_PITCH)                   // 66560
#define XS_OFF   (HS_OFF + 32u * PB_PITCH)          // 99840
#define XS_PITCH 272                                // 68 floats per row (16B-mult)
#define XS_BUF   (32u * XS_PITCH)                   // 8704
#define SMEM_B_BYTES (XS_OFF + 2 * XS_BUF + 64)     // ~117312

__global__ __launch_bounds__(128, 1) void lstm_rec_kernel(
    const float* __restrict__ Wh,
    float* __restrict__ out)
{
    extern __shared__ uint8_t smB[];
    const uint32_t sb = (uint32_t)__cvta_generic_to_shared(smB);

    const int tid  = threadIdx.x;
    const int warp = tid >> 5;
    const int lane = tid & 31;
    const int g    = lane >> 2;
    const int t    = lane & 3;

    const int bi = blockIdx.x >> 5;
    const int bj = blockIdx.x & 31;
    const int b0 = bi * 32;
    const int j0 = bj * 16;

    // one-time: Wh slice -> SMEM fp16, gate-interleaved rows.
    // SMEM row n: w = n>>4, p = n&15, c = p>>2 (h-col within warp), gate = p&3.
    for (int idx = tid; idx < 64 * 512; idx += 128) {
        int n = idx >> 9;
        int k = idx & 511;
        int w = n >> 4, p = n & 15;
        int grow = (p & 3) * HID + j0 + w * 4 + (p >> 2);
        *(__half*)(smB + WHS_OFF + (uint32_t)n * PB_PITCH + (uint32_t)k * 2) =
            __float2half_rn(Wh[(size_t)grow * HID + k]);
    }

    // ldmatrix bases (unchanged addressing; only B row contents changed)
    uint32_t aA0 = sb + HS_OFF + (uint32_t)((lane & 15) * PB_PITCH + (lane >> 4) * 16);
    uint32_t aA1 = sb + HS_OFF + (uint32_t)((16 + (lane & 15)) * PB_PITCH + (lane >> 4) * 16);
    uint32_t aB  = sb + WHS_OFF
                 + (uint32_t)((warp * 16 + (lane & 7) + ((lane >> 4) << 3)) * PB_PITCH
                              + ((lane >> 3) & 1) * 16);

    // element coordinates for this thread's 4 (mt,nt) elements
    // row_local = mt*16 + g + ((t&1)<<3); col jl = warp*4 + (t>>1) + 2*nt
    const int odd = t & 1;

    float cst[2][2] = {{0.f, 0.f}, {0.f, 0.f}};   // cell state per (mt,nt)

    // Xs prefetch helper: 512 16B-chunks per buffer, 4 per thread
    auto issue_xs = [&](int ts_next) {
        uint32_t base = XS_OFF + (uint32_t)(ts_next & 1) * XS_BUF;
        const float* src_base = g_xg + (size_t)ts_next * (BATCH * G4);
#pragma unroll
        for (int i = 0; i < 4; i++) {
            int id = i * 128 + tid;        // 0..511
            int r  = id >> 4;              // 0..31
            int u  = id & 15;              // 16B unit within row (64 floats)
            cp16(sb + base + (uint32_t)(r * XS_PITCH + u * 16),
                 src_base + (size_t)(b0 + r) * G4 + (u >> 2) * HID + j0 + (u & 3) * 4);
        }
        cp_commit();
    };

    // preload Xs[0]
    issue_xs(0);
    __syncthreads();   // Whs stores visible before first gemm (and Xs commit done)

    float acc[2][2][4];

    for (int ts = 0; ts < T_STEPS; ts++) {
        if (ts > 0) {
            // ---- wait for all 32 same-bi blocks to publish h_{ts-1} ----
            if (tid < 32) {
                const unsigned int* fp = &g_flag[bi][ts - 1][tid];
                unsigned v;
                do {
                    asm volatile("ld.acquire.gpu.global.u32 %0, [%1];"
                                 : "=r"(v) : "l"(fp) : "memory");
                } while (!v);
            }
            __syncthreads();

            // ---- h_{ts-1} fp16 tile -> SMEM (32 x 1024B) ----
            const __half* hsrc = g_hbuf[(ts - 1) & 1] + (size_t)b0 * HID;
#pragma unroll
            for (int i = 0; i < 16; i++) {
                int id = i * 128 + tid;     // 0..2047 16B chunks
                int r  = id >> 6;
                int u  = id & 63;
                cp16(sb + HS_OFF + (uint32_t)(r * PB_PITCH + u * 16),
                     hsrc + (size_t)r * HID + u * 8);
            }
            cp_commit();
            cp_wait<0>();       // drains h AND the Xs[ts] group
            __syncthreads();

            // ---- 32x64x512 fp16 GEMM: 4 warps, 32 k16-steps ----
#pragma unroll
            for (int mt = 0; mt < 2; mt++)
#pragma unroll
                for (int nt = 0; nt < 2; nt++)
#pragma unroll
                    for (int q = 0; q < 4; q++) acc[mt][nt][q] = 0.0f;

#pragma unroll 4
            for (int s = 0; s < 32; s++) {
                uint32_t ko = (uint32_t)(s * 32);
                uint32_t a0[4], a1[4], bb[4];
                ldsm4(a0, aA0 + ko);
                ldsm4(a1, aA1 + ko);
                ldsm4(bb, aB + ko);
                mma_f16(acc[0][0], a0[0], a0[1], a0[2], a0[3], bb[0], bb[1]);
                mma_f16(acc[0][1], a0[0], a0[1], a0[2], a0[3], bb[2], bb[3]);
                mma_f16(acc[1][0], a1[0], a1[1], a1[2], a1[3], bb[0], bb[1]);
                mma_f16(acc[1][1], a1[0], a1[1], a1[2], a1[3], bb[2], bb[3]);
            }
        } else {
            cp_wait<0>();       // Xs[0]
            __syncthreads();
#pragma unroll
            for (int mt = 0; mt < 2; mt++)
#pragma unroll
                for (int nt = 0; nt < 2; nt++)
#pragma unroll
                    for (int q = 0; q < 4; q++) acc[mt][nt][q] = 0.0f;
        }

        // ---- warp-local elementwise: shuffle gate quadruples, 4 elems/thread
        const float* Xs = (const float*)(smB + XS_OFF + (uint32_t)(ts & 1) * XS_BUF);
        float hout[2][2];
#pragma unroll
        for (int mt = 0; mt < 2; mt++) {
#pragma unroll
            for (int nt = 0; nt < 2; nt++) {
                float q0 = acc[mt][nt][0], q1 = acc[mt][nt][1];
                float q2 = acc[mt][nt][2], q3 = acc[mt][nt][3];
                // even lane sends (q2,q3)=i/f(r+8); odd sends (q0,q1)=g/o(r)
                float sx = odd ? q0 : q2;
                float sy = odd ? q1 : q3;
                float rx = __shfl_xor_sync(0xffffffffu, sx, 1);
                float ry = __shfl_xor_sync(0xffffffffu, sy, 1);
                float gi = odd ? rx : q0;
                float gf = odd ? ry : q1;
                float gg = odd ? q2 : rx;
                float go = odd ? q3 : ry;

                int rl = mt * 16 + g + (odd << 3);
                int jl = warp * 4 + (t >> 1) + 2 * nt;
                const float* xrow = Xs + rl * 68 + jl;
                gi += xrow[0];
                gf += xrow[16];
                gg += xrow[32];
                go += xrow[48];

                float iv = fsigmoid(gi), fv = fsigmoid(gf);
                float gv = ftanh(gg),    ov = fsigmoid(go);
                float cn = cst[mt][nt] * fv + iv * gv;
                cst[mt][nt] = cn;
                float h = ov * ftanh(cn);
                hout[mt][nt] = h;

                g_hbuf[ts & 1][(size_t)(b0 + rl) * HID + j0 + jl] = __float2half_rn(h);
            }
        }

        __syncthreads();   // all hbuf stores issued before the release

        if (ts < T_STEPS - 1) {
            if (tid == 0) {
                asm volatile("st.release.gpu.global.u32 [%0], %1;"
                             :: "l"(&g_flag[bi][ts][bj]), "r"(1u) : "memory");
            }
        }

        // out fp32 stores — off the inter-block critical path
        {
            float* obase = out + (size_t)ts * (BATCH * HID);
#pragma unroll
            for (int mt = 0; mt < 2; mt++)
#pragma unroll
                for (int nt = 0; nt < 2; nt++) {
                    int rl = mt * 16 + g + (odd << 3);
                    int jl = warp * 4 + (t >> 1) + 2 * nt;
                    obase[(size_t)(b0 + rl) * HID + j0 + jl] = hout[mt][nt];
                }
        }

        // prefetch Xs[ts+1] (independent of other blocks; overlaps their work)
        if (ts + 1 < T_STEPS) issue_xs(ts + 1);
    }

    // ---- exit: last block resets barrier state for next graph replay ----
    __syncthreads();
    volatile unsigned* rflag = (volatile unsigned*)(smB + XS_OFF);
    if (tid == 0) {
        unsigned old;
        asm volatile("atom.acq_rel.gpu.add.u32 %0, [%1], 1;"
                     : "=r"(old) : "l"(&g_exit) : "memory");
        *rflag = (old == 127u) ? 1u : 0u;
    }
    __syncthreads();
    if (*rflag != 0u) {
        unsigned int* fl = &g_flag[0][0][0];
        for (int i = tid; i < 4 * T_STEPS * 32; i += 128) fl[i] = 0u;
        __threadfence();
        if (tid == 0) g_exit = 0u;
    }
}

// ===========================================================================
// Launch
// ===========================================================================
extern "C" void kernel_launch(void* const* d_in, const int* in_sizes, int n_in,
                              void* d_out, int out_size)
{
    (void)in_sizes; (void)n_in; (void)out_size;
    const float* x  = (const float*)d_in[0];
    const float* Wx = (const float*)d_in[1];
    const float* bx = (const float*)d_in[2];
    const float* Wh = (const float*)d_in[3];
    const float* bh = (const float*)d_in[4];
    float* out = (float*)d_out;

    __half* xh;  cudaGetSymbolAddress((void**)&xh,  g_xh);
    __half* wxh; cudaGetSymbolAddress((void**)&wxh, g_wxh);

    cudaFuncSetAttribute(gemm_xg_kernel,
                         cudaFuncAttributeMaxDynamicSharedMemorySize, SMEM_A_BYTES);
    cudaFuncSetAttribute(lstm_rec_kernel,
                         cudaFuncAttributeMaxDynamicSharedMemorySize, SMEM_B_BYTES);

    cvt_f16_kernel<<<2048, 256>>>(x,  xh,  (size_t)T_STEPS * BATCH * DIN / 4);
    cvt_f16_kernel<<<512,  256>>>(Wx, wxh, (size_t)G4 * DIN / 4);

    gemm_xg_kernel<<<dim3(G4 / 128, (T_STEPS * BATCH) / 128), 256, SMEM_A_BYTES>>>(bx, bh);

    lstm_rec_kernel<<<128, 128, SMEM_B_BYTES>>>(Wh, out);
}

// round 8
// speedup vs baseline: 2.0757x; 1.2431x over previous
#include <cuda_runtime.h>
#include <cuda_fp16.h>
#include <cstdint>
#include <cstddef>

// Problem constants
#define T_STEPS 512
#define BATCH   128
#define DIN     512
#define HID     512
#define G4      2048   // 4*HID

// ---------------------------------------------------------------------------
// Device-global scratch (allocation-free rule)
// ---------------------------------------------------------------------------
__device__ __half g_xh[(size_t)T_STEPS * BATCH * DIN];    // x as fp16
__device__ __half g_hbuf[2][(size_t)BATCH * HID];         // h as fp16, dbl-buf
__device__ unsigned int g_flag[4][T_STEPS][32];           // barrier flags
__device__ unsigned int g_exit;

// ---------------------------------------------------------------------------
// helpers
// ---------------------------------------------------------------------------
__device__ __forceinline__ void mma_f16(float* d,
    uint32_t a0, uint32_t a1, uint32_t a2, uint32_t a3,
    uint32_t b0, uint32_t b1)
{
    asm volatile(
        "mma.sync.aligned.m16n8k16.row.col.f32.f16.f16.f32 "
        "{%0,%1,%2,%3}, {%4,%5,%6,%7}, {%8,%9}, {%0,%1,%2,%3};\n"
        : "+f"(d[0]), "+f"(d[1]), "+f"(d[2]), "+f"(d[3])
        : "r"(a0), "r"(a1), "r"(a2), "r"(a3), "r"(b0), "r"(b1));
}

__device__ __forceinline__ void ldsm4(uint32_t* r, uint32_t addr) {
    asm volatile(
        "ldmatrix.sync.aligned.m8n8.x4.shared.b16 {%0,%1,%2,%3}, [%4];"
        : "=r"(r[0]), "=r"(r[1]), "=r"(r[2]), "=r"(r[3]) : "r"(addr));
}

__device__ __forceinline__ void cp16(uint32_t dst, const void* src) {
    asm volatile("cp.async.cg.shared.global [%0], [%1], 16;" :: "r"(dst), "l"(src));
}
__device__ __forceinline__ void cp_commit() {
    asm volatile("cp.async.commit_group;");
}
template <int N>
__device__ __forceinline__ void cp_wait() {
    asm volatile("cp.async.wait_group %0;" :: "n"(N));
}

__device__ __forceinline__ float fsigmoid(float x) {
    return __fdividef(1.0f, 1.0f + __expf(-x));
}
__device__ __forceinline__ float ftanh(float x) {
    float e = __expf(-2.0f * x);
    return __fdividef(2.0f, 1.0f + e) - 1.0f;
}

// ===========================================================================
// Prologue: fp32 -> fp16 conversion (x only; W slices converted in-kernel)
// ===========================================================================
__global__ void cvt_f16_kernel(const float* __restrict__ src,
                               __half* __restrict__ dst, size_t n4)
{
    size_t i = (size_t)blockIdx.x * blockDim.x + threadIdx.x;
    size_t stride = (size_t)gridDim.x * blockDim.x;
    for (; i < n4; i += stride) {
        float4 v = ((const float4*)src)[i];
        __half2 lo = __floats2half2_rn(v.x, v.y);
        __half2 hi = __floats2half2_rn(v.z, v.w);
        uint2 u;
        u.x = *(uint32_t*)&lo;
        u.y = *(uint32_t*)&hi;
        ((uint2*)dst)[i] = u;
    }
}

// ===========================================================================
// Fused persistent LSTM kernel, 128 blocks x 128 threads.
//   Block (bi,bj) owns 32 batch rows x 16 h-cols. Both the recurrent GEMM
//   (h_{t-1} @ Wh^T) and the input-projection GEMM (x_{t+1} @ Wx^T) are
//   32x64x512 fp16 mma with IDENTICAL gate-interleaved B layout, so the xg
//   accumulator sums into the recurrent accumulator pre-shuffle and the
//   input projection runs in the post-release idle window of each step.
//   No xg tensor, no separate phase-A kernel.
// SMEM:
//   Whs [64][PB_PITCH]  gate-interleaved Wh slice (fp16)
//   Wxs [64][PB_PITCH]  gate-interleaved Wx slice (fp16)
//   Hs  [32][PB_PITCH]  h_{t-1} tile (fp16)
//   Xh  [32][PB_PITCH]  x_{t+1} tile (fp16)
// ===========================================================================
#define PB_PITCH 1040                               // 512 halves + 16B pad
#define WHS_OFF  0u
#define WXS_OFF  (64u * PB_PITCH)                   // 66560
#define HS_OFF   (WXS_OFF + 64u * PB_PITCH)         // 133120
#define XH_OFF   (HS_OFF + 32u * PB_PITCH)          // 166400
#define SMEM_B_BYTES (XH_OFF + 32u * PB_PITCH + 64) // 199744

__global__ __launch_bounds__(128, 1) void lstm_rec_kernel(
    const float* __restrict__ Wh,
    const float* __restrict__ Wx,
    const float* __restrict__ bxp,
    const float* __restrict__ bhp,
    float* __restrict__ out)
{
    extern __shared__ uint8_t smB[];
    const uint32_t sb = (uint32_t)__cvta_generic_to_shared(smB);

    const int tid  = threadIdx.x;
    const int warp = tid >> 5;
    const int lane = tid & 31;
    const int g    = lane >> 2;
    const int t    = lane & 3;
    const int odd  = t & 1;

    const int bi = blockIdx.x >> 5;
    const int bj = blockIdx.x & 31;
    const int b0 = bi * 32;
    const int j0 = bj * 16;

    // ---- one-time: Wh and Wx slices -> SMEM fp16, gate-interleaved rows ----
    // SMEM row n: w = n>>4, p = n&15 -> gate = p&3, h-col = j0 + w*4 + (p>>2)
    for (int idx = tid; idx < 64 * 512; idx += 128) {
        int n = idx >> 9;
        int k = idx & 511;
        int w = n >> 4, p = n & 15;
        int grow = (p & 3) * HID + j0 + w * 4 + (p >> 2);
        *(__half*)(smB + WHS_OFF + (uint32_t)n * PB_PITCH + (uint32_t)k * 2) =
            __float2half_rn(Wh[(size_t)grow * HID + k]);
        *(__half*)(smB + WXS_OFF + (uint32_t)n * PB_PITCH + (uint32_t)k * 2) =
            __float2half_rn(Wx[(size_t)grow * DIN + k]);
    }

    // ---- bias registers: per (nt, gate) for this thread's two h-cols ----
    float bias[2][4];
#pragma unroll
    for (int nt = 0; nt < 2; nt++) {
        int jc = j0 + warp * 4 + (t >> 1) + 2 * nt;
#pragma unroll
        for (int gate = 0; gate < 4; gate++)
            bias[nt][gate] = bxp[gate * HID + jc] + bhp[gate * HID + jc];
    }

    // ---- ldmatrix bases ----
    uint32_t rowsel = (uint32_t)((lane & 15) * PB_PITCH + (lane >> 4) * 16);
    uint32_t aH0 = sb + HS_OFF + rowsel;
    uint32_t aH1 = sb + HS_OFF + (uint32_t)(16 * PB_PITCH) + rowsel;
    uint32_t aX0 = sb + XH_OFF + rowsel;
    uint32_t aX1 = sb + XH_OFF + (uint32_t)(16 * PB_PITCH) + rowsel;
    uint32_t brow = (uint32_t)((warp * 16 + (lane & 7) + ((lane >> 4) << 3)) * PB_PITCH
                               + ((lane >> 3) & 1) * 16);
    uint32_t aBh = sb + WHS_OFF + brow;
    uint32_t aBx = sb + WXS_OFF + brow;

    // x tile loader (16 chunks of 16B per thread = 32KB)
    auto issue_x = [&](int tsn) {
        const __half* src = g_xh + ((size_t)tsn * BATCH + b0) * DIN;
#pragma unroll
        for (int i = 0; i < 16; i++) {
            int id = i * 128 + tid;
            int r  = id >> 6;
            int u  = id & 63;
            cp16(sb + XH_OFF + (uint32_t)(r * PB_PITCH + u * 16),
                 src + (size_t)r * DIN + u * 8);
        }
        cp_commit();
    };

    float accx[2][2][4];
    float accr[2][2][4];
    float cst[2][2] = {{0.f, 0.f}, {0.f, 0.f}};

    // xg gemm: Xh @ Wxs -> accx
    auto xg_gemm = [&]() {
#pragma unroll
        for (int mt = 0; mt < 2; mt++)
#pragma unroll
            for (int nt = 0; nt < 2; nt++)
#pragma unroll
                for (int q = 0; q < 4; q++) accx[mt][nt][q] = 0.0f;
#pragma unroll 4
        for (int s = 0; s < 32; s++) {
            uint32_t ko = (uint32_t)(s * 32);
            uint32_t a0[4], a1[4], bb[4];
            ldsm4(a0, aX0 + ko);
            ldsm4(a1, aX1 + ko);
            ldsm4(bb, aBx + ko);
            mma_f16(accx[0][0], a0[0], a0[1], a0[2], a0[3], bb[0], bb[1]);
            mma_f16(accx[0][1], a0[0], a0[1], a0[2], a0[3], bb[2], bb[3]);
            mma_f16(accx[1][0], a1[0], a1[1], a1[2], a1[3], bb[0], bb[1]);
            mma_f16(accx[1][1], a1[0], a1[1], a1[2], a1[3], bb[2], bb[3]);
        }
    };

    // ---- prologue: x[0] -> Xh, xg-gemm for ts=0 ----
    issue_x(0);
    cp_wait<0>();
    __syncthreads();        // Whs/Wxs stores + Xh visible to all warps
    xg_gemm();

    for (int ts = 0; ts < T_STEPS; ts++) {
        if (ts > 0) {
            // ---- wait for peers to publish h_{ts-1} ----
            if (tid < 32) {
                const unsigned int* fp = &g_flag[bi][ts - 1][tid];
                unsigned v;
                do {
                    asm volatile("ld.acquire.gpu.global.u32 %0, [%1];"
                                 : "=r"(v) : "l"(fp) : "memory");
                } while (!v);
            }
            __syncthreads();   // also guards Xh reuse: all warps past xg_gemm

            // ---- h_{ts-1} tile -> Hs (group 0) ----
            const __half* hsrc = g_hbuf[(ts - 1) & 1] + (size_t)b0 * HID;
#pragma unroll
            for (int i = 0; i < 16; i++) {
                int id = i * 128 + tid;
                int r  = id >> 6;
                int u  = id & 63;
                cp16(sb + HS_OFF + (uint32_t)(r * PB_PITCH + u * 16),
                     hsrc + (size_t)r * HID + u * 8);
            }
            cp_commit();
        }

        // ---- x[ts+1] tile -> Xh (last group) ----
        if (ts + 1 < T_STEPS) issue_x(ts + 1);

        if (ts > 0) {
            if (ts + 1 < T_STEPS) { cp_wait<1>(); } else { cp_wait<0>(); }
            __syncthreads();

            // ---- recurrent GEMM: Hs @ Whs -> accr ----
#pragma unroll
            for (int mt = 0; mt < 2; mt++)
#pragma unroll
                for (int nt = 0; nt < 2; nt++)
#pragma unroll
                    for (int q = 0; q < 4; q++) accr[mt][nt][q] = accx[mt][nt][q];

#pragma unroll 4
            for (int s = 0; s < 32; s++) {
                uint32_t ko = (uint32_t)(s * 32);
                uint32_t a0[4], a1[4], bb[4];
                ldsm4(a0, aH0 + ko);
                ldsm4(a1, aH1 + ko);
                ldsm4(bb, aBh + ko);
                mma_f16(accr[0][0], a0[0], a0[1], a0[2], a0[3], bb[0], bb[1]);
                mma_f16(accr[0][1], a0[0], a0[1], a0[2], a0[3], bb[2], bb[3]);
                mma_f16(accr[1][0], a1[0], a1[1], a1[2], a1[3], bb[0], bb[1]);
                mma_f16(accr[1][1], a1[0], a1[1], a1[2], a1[3], bb[2], bb[3]);
            }
        } else {
#pragma unroll
            for (int mt = 0; mt < 2; mt++)
#pragma unroll
                for (int nt = 0; nt < 2; nt++)
#pragma unroll
                    for (int q = 0; q < 4; q++) accr[mt][nt][q] = accx[mt][nt][q];
        }

        // ---- warp-local elementwise (gate shuffle), 4 elems/thread ----
        float hout[2][2];
#pragma unroll
        for (int mt = 0; mt < 2; mt++) {
#pragma unroll
            for (int nt = 0; nt < 2; nt++) {
                float q0 = accr[mt][nt][0], q1 = accr[mt][nt][1];
                float q2 = accr[mt][nt][2], q3 = accr[mt][nt][3];
                float sx = odd ? q0 : q2;
                float sy = odd ? q1 : q3;
                float rx = __shfl_xor_sync(0xffffffffu, sx, 1);
                float ry = __shfl_xor_sync(0xffffffffu, sy, 1);
                float gi = (odd ? rx : q0) + bias[nt][0];
                float gf = (odd ? ry : q1) + bias[nt][1];
                float gg = (odd ? q2 : rx) + bias[nt][2];
                float go = (odd ? q3 : ry) + bias[nt][3];

                float iv = fsigmoid(gi), fv = fsigmoid(gf);
                float gv = ftanh(gg),    ov = fsigmoid(go);
                float cn = cst[mt][nt] * fv + iv * gv;
                cst[mt][nt] = cn;
                float h = ov * ftanh(cn);
                hout[mt][nt] = h;

                int rl = mt * 16 + g + (odd << 3);
                int jl = warp * 4 + (t >> 1) + 2 * nt;
                g_hbuf[ts & 1][(size_t)(b0 + rl) * HID + j0 + jl] = __float2half_rn(h);
            }
        }

        __syncthreads();   // all hbuf stores issued before release

        if (ts < T_STEPS - 1) {
            if (tid == 0) {
                asm volatile("st.release.gpu.global.u32 [%0], %1;"
                             :: "l"(&g_flag[bi][ts][bj]), "r"(1u) : "memory");
            }
        }

        // ---- out fp32 stores (off the inter-block critical path) ----
        {
            float* obase = out + (size_t)ts * (BATCH * HID);
#pragma unroll
            for (int mt = 0; mt < 2; mt++)
#pragma unroll
                for (int nt = 0; nt < 2; nt++) {
                    int rl = mt * 16 + g + (odd << 3);
                    int jl = warp * 4 + (t >> 1) + 2 * nt;
                    obase[(size_t)(b0 + rl) * HID + j0 + jl] = hout[mt][nt];
                }
        }

        // ---- input projection for ts+1 in the sync idle window ----
        if (ts + 1 < T_STEPS) {
            cp_wait<0>();      // x[ts+1] landed (own chunks)
            __syncthreads();   // everyone's chunks landed
            xg_gemm();
        }
    }

    // ---- exit: last block resets barrier state for next graph replay ----
    __syncthreads();
    volatile unsigned* rflag = (volatile unsigned*)(smB + XH_OFF);
    if (tid == 0) {
        unsigned old;
        asm volatile("atom.acq_rel.gpu.add.u32 %0, [%1], 1;"
                     : "=r"(old) : "l"(&g_exit) : "memory");
        *rflag = (old == 127u) ? 1u : 0u;
    }
    __syncthreads();
    if (*rflag != 0u) {
        unsigned int* fl = &g_flag[0][0][0];
        for (int i = tid; i < 4 * T_STEPS * 32; i += 128) fl[i] = 0u;
        __threadfence();
        if (tid == 0) g_exit = 0u;
    }
}

// ===========================================================================
// Launch
// ===========================================================================
extern "C" void kernel_launch(void* const* d_in, const int* in_sizes, int n_in,
                              void* d_out, int out_size)
{
    (void)in_sizes; (void)n_in; (void)out_size;
    const float* x  = (const float*)d_in[0];
    const float* Wx = (const float*)d_in[1];
    const float* bx = (const float*)d_in[2];
    const float* Wh = (const float*)d_in[3];
    const float* bh = (const float*)d_in[4];
    float* out = (float*)d_out;

    __half* xh;  cudaGetSymbolAddress((void**)&xh,  g_xh);

    cudaFuncSetAttribute(lstm_rec_kernel,
                         cudaFuncAttributeMaxDynamicSharedMemorySize, SMEM_B_BYTES);

    // x: fp32 -> fp16
    cvt_f16_kernel<<<2048, 256>>>(x, xh, (size_t)T_STEPS * BATCH * DIN / 4);

    // fused persistent LSTM
    lstm_rec_kernel<<<128, 128, SMEM_B_BYTES>>>(Wh, Wx, bx, bh, out);
}